// round 12
// baseline (speedup 1.0000x reference)
#include <cuda_runtime.h>
#include <cuda_bf16.h>
#include <cuda_fp16.h>
#include <cstdint>

#define N_NODES 100000
#define D 128

// ---------------- scratch (device globals: no allocations allowed) ----------
__device__ int    g_rowptr[N_NODES + 1];
__device__ __half g_hW[(size_t)N_NODES * D];   // h @ W.T in fp16, 25.6 MB
// Pre-swizzled W fragments for mma.sync m16n8k16 fp16.
__device__ uint2 g_Whf[8 * 16 * 32];

// ---------------- Kernel 1: row_ptr via scatter over sorted rows ------------
__global__ void rowptr_kernel(const int* __restrict__ rows, int n_edges) {
    int e = blockIdx.x * blockDim.x + threadIdx.x;
    if (e >= n_edges) return;
    int b = __ldg(&rows[e]);
    if (e == 0) {
        for (int i = 0; i <= b; i++) g_rowptr[i] = 0;
    } else {
        int a = __ldg(&rows[e - 1]);
        for (int i = a + 1; i <= b; i++) g_rowptr[i] = e;
    }
    if (e == n_edges - 1) {
        for (int i = b + 1; i <= N_NODES; i++) g_rowptr[i] = n_edges;
    }
}

// ---------------- Kernel 1b: W fragment prep (fp16) -------------------------
__device__ __forceinline__ uint32_t pack2_h16(float x, float y) {
    __half2 v = __floats2half2_rn(x, y);
    return *(uint32_t*)&v;
}

__global__ void wprep_kernel(const float* __restrict__ W) {
    int t = blockIdx.x * blockDim.x + threadIdx.x;   // 0..4095
    if (t >= 8 * 16 * 32) return;
    int lane  = t & 31;
    int ntile = (t >> 5) & 15;
    int kstep = t >> 9;

    int n  = ntile * 8 + (lane >> 2);
    int k0 = kstep * 16 + (lane & 3) * 2;

    float w00 = __ldg(&W[n * 128 + k0]);
    float w01 = __ldg(&W[n * 128 + k0 + 1]);
    float w10 = __ldg(&W[n * 128 + k0 + 8]);
    float w11 = __ldg(&W[n * 128 + k0 + 9]);

    uint2 f;
    f.x = pack2_h16(w00, w01);
    f.y = pack2_h16(w10, w11);
    g_Whf[t] = f;
}

// ---------------- Kernel 2: g = h @ W.T, smem-staged fp16 mma ----------------
// (unchanged from R10/R11 — measured improvement)
#define MTILE 64
#define APAD  136

__device__ __forceinline__ void mma_f16(float* c, const uint32_t* a, uint2 b) {
    asm volatile(
        "mma.sync.aligned.m16n8k16.row.col.f32.f16.f16.f32 "
        "{%0,%1,%2,%3}, {%4,%5,%6,%7}, {%8,%9}, {%0,%1,%2,%3};"
        : "+f"(c[0]), "+f"(c[1]), "+f"(c[2]), "+f"(c[3])
        : "r"(a[0]), "r"(a[1]), "r"(a[2]), "r"(a[3]), "r"(b.x), "r"(b.y));
}

__global__ void __launch_bounds__(128, 4) gemm_kernel(
    const float* __restrict__ A)   // h [N_NODES, 128]
{
    __shared__ __half sA[MTILE * APAD];   // 17.4 KB

    const int tid    = threadIdx.x;
    const int lane   = tid & 31;
    const int warp   = tid >> 5;
    const int m_base = blockIdx.x * MTILE;

    #pragma unroll
    for (int q = 0; q < 16; q++) {
        int idx = q * 128 + tid;          // 0..2047
        int row = idx >> 5;
        int c4  = idx & 31;
        int rsrc = min(m_base + row, N_NODES - 1);
        float4 v = __ldg(&((const float4*)A)[(size_t)rsrc * 32 + c4]);
        __half2 p0 = __floats2half2_rn(v.x, v.y);
        __half2 p1 = __floats2half2_rn(v.z, v.w);
        *(__half2*)&sA[row * APAD + c4 * 4]     = p0;
        *(__half2*)&sA[row * APAD + c4 * 4 + 2] = p1;
    }
    __syncthreads();

    const int grp  = lane >> 2;
    const int quad = lane & 3;
    const int mrow = (warp >> 1) * 32;
    const int ntb  = (warp & 1) * 8;

    float acc[2][8][4];
    #pragma unroll
    for (int f = 0; f < 2; f++)
        #pragma unroll
        for (int nt = 0; nt < 8; nt++)
            #pragma unroll
            for (int i = 0; i < 4; i++) acc[f][nt][i] = 0.f;

    #pragma unroll
    for (int kstep = 0; kstep < 8; kstep++) {
        int kb = kstep * 16 + quad * 2;
        uint32_t a[2][4];
        #pragma unroll
        for (int f = 0; f < 2; f++) {
            int r = mrow + f * 16 + grp;
            a[f][0] = *(uint32_t*)&sA[r * APAD + kb];
            a[f][1] = *(uint32_t*)&sA[(r + 8) * APAD + kb];
            a[f][2] = *(uint32_t*)&sA[r * APAD + kb + 8];
            a[f][3] = *(uint32_t*)&sA[(r + 8) * APAD + kb + 8];
        }
        #pragma unroll
        for (int nt = 0; nt < 8; nt++) {
            uint2 wh = __ldg(&g_Whf[(kstep * 16 + ntb + nt) * 32 + lane]);
            mma_f16(acc[0][nt], a[0], wh);
            mma_f16(acc[1][nt], a[1], wh);
        }
    }
    __syncthreads();

    #pragma unroll
    for (int f = 0; f < 2; f++) {
        #pragma unroll
        for (int nt = 0; nt < 8; nt++) {
            int col = (ntb + nt) * 8 + quad * 2;
            int r0  = mrow + f * 16 + grp;
            *(__half2*)&sA[r0 * APAD + col] =
                __floats2half2_rn(acc[f][nt][0], acc[f][nt][1]);
            *(__half2*)&sA[(r0 + 8) * APAD + col] =
                __floats2half2_rn(acc[f][nt][2], acc[f][nt][3]);
        }
    }
    __syncthreads();

    #pragma unroll
    for (int q = 0; q < 8; q++) {
        int idx = q * 128 + tid;          // 0..1023
        int row = idx >> 4;
        int c16 = idx & 15;
        int rdst = m_base + row;
        if (rdst < N_NODES) {
            uint4 v = *(uint4*)&sA[row * APAD + c16 * 8];
            *(uint4*)&g_hW[(size_t)rdst * 128 + c16 * 8] = v;
        }
    }
}

// ---------------- Kernel 3: SpMM, half-warp per node, f32x2 FMA -------------
// Half-warp (16 lanes) per node; lane owns 8 features (uint4 = 16B fp16).
// Edge trips of 16, last trip bounded to jmax and walked in unrolled quads
// (cuts padding waste 37% -> ~15%). Accumulation in packed f32x2 (FFMA2).
typedef unsigned long long u64;

__device__ __forceinline__ u64 pack_f32x2(float lo, float hi) {
    u64 r;
    asm("mov.b64 %0, {%1, %2};" : "=l"(r) : "f"(lo), "f"(hi));
    return r;
}
__device__ __forceinline__ void unpack_f32x2(u64 p, float& lo, float& hi) {
    asm("mov.b64 {%0, %1}, %2;" : "=f"(lo), "=f"(hi) : "l"(p));
}
__device__ __forceinline__ u64 fma_f32x2(u64 a, u64 b, u64 c) {
    u64 d;
    asm("fma.rn.f32x2 %0, %1, %2, %3;" : "=l"(d) : "l"(a), "l"(b), "l"(c));
    return d;
}

__global__ void __launch_bounds__(256) spmm_kernel(
    const int*   __restrict__ cols,
    const float* __restrict__ vals,
    const float* __restrict__ bias,
    float*       __restrict__ out)
{
    const int warp_id = (blockIdx.x * blockDim.x + threadIdx.x) >> 5;
    const unsigned lane = threadIdx.x & 31;
    const unsigned hl   = lane & 15;          // lane within half-warp
    const int nid = warp_id * 2 + (int)(lane >> 4);
    if (warp_id * 2 >= N_NODES) return;

    int start = 0, end = 0;
    if (nid < N_NODES) {
        start = g_rowptr[nid];
        end   = g_rowptr[nid + 1];
    }
    const int deg  = end - start;
    const int odeg = __shfl_xor_sync(0xffffffffu, deg, 16);
    const int maxd = max(deg, odeg);          // warp-uniform

    const uint4* __restrict__ g4 = ((const uint4*)g_hW) + hl;   // row = 16 uint4

    u64 acc0 = 0, acc1 = 0, acc2 = 0, acc3 = 0;   // packed {0.f,0.f}

    for (int base = 0; base < maxd; base += 16) {
        int e = start + base + (int)hl;
        int   c = 0; float v = 0.f;
        if (e < end) {
            c = __ldg(&cols[e]);
            v = __ldg(&vals[e]);
        }
        const int jmax = min(16, maxd - base);   // warp-uniform
        for (int j0 = 0; j0 < jmax; j0 += 4) {
            #pragma unroll
            for (int j = 0; j < 4; j++) {
                unsigned cj = (unsigned)__shfl_sync(0xffffffffu, c, j0 + j, 16);
                float    vj = __shfl_sync(0xffffffffu, v, j0 + j, 16);
                u64 v2 = pack_f32x2(vj, vj);
                uint4 raw = __ldg(&g4[cj * 16u]);
                float2 f0 = __half22float2(*(__half2*)&raw.x);
                float2 f1 = __half22float2(*(__half2*)&raw.y);
                float2 f2 = __half22float2(*(__half2*)&raw.z);
                float2 f3 = __half22float2(*(__half2*)&raw.w);
                acc0 = fma_f32x2(v2, pack_f32x2(f0.x, f0.y), acc0);
                acc1 = fma_f32x2(v2, pack_f32x2(f1.x, f1.y), acc1);
                acc2 = fma_f32x2(v2, pack_f32x2(f2.x, f2.y), acc2);
                acc3 = fma_f32x2(v2, pack_f32x2(f3.x, f3.y), acc3);
            }
        }
    }

    if (nid < N_NODES) {
        float a0, a1, a2, a3, a4, a5, a6, a7;
        unpack_f32x2(acc0, a0, a1);
        unpack_f32x2(acc1, a2, a3);
        unpack_f32x2(acc2, a4, a5);
        unpack_f32x2(acc3, a6, a7);
        const float4* b4 = ((const float4*)bias) + hl * 2;
        float4 ba = __ldg(&b4[0]);
        float4 bb = __ldg(&b4[1]);
        float4 o0, o1;
        o0.x = fmaxf(a0 + ba.x, 0.f);
        o0.y = fmaxf(a1 + ba.y, 0.f);
        o0.z = fmaxf(a2 + ba.z, 0.f);
        o0.w = fmaxf(a3 + ba.w, 0.f);
        o1.x = fmaxf(a4 + bb.x, 0.f);
        o1.y = fmaxf(a5 + bb.y, 0.f);
        o1.z = fmaxf(a6 + bb.z, 0.f);
        o1.w = fmaxf(a7 + bb.w, 0.f);
        float4* orow = ((float4*)out) + (size_t)nid * 32 + hl * 2;
        orow[0] = o0;
        orow[1] = o1;
    }
}

// ---------------- launch ----------------------------------------------------
extern "C" void kernel_launch(void* const* d_in, const int* in_sizes, int n_in,
                              void* d_out, int out_size)
{
    const int*   edge_rows = (const int*)  d_in[0];
    const int*   edge_cols = (const int*)  d_in[1];
    const float* edge_vals = (const float*)d_in[2];
    const float* h         = (const float*)d_in[3];
    const float* W         = (const float*)d_in[4];
    const float* b         = (const float*)d_in[5];
    float*       out       = (float*)d_out;

    const int n_edges = in_sizes[0];

    // 1) row_ptr (scatter) + W fragment prep
    {
        int threads = 256;
        int blocks  = (n_edges + threads - 1) / threads;
        rowptr_kernel<<<blocks, threads>>>(edge_rows, n_edges);
        wprep_kernel<<<16, 256>>>(W);
    }

    // 2) g = h @ W.T  (smem-staged fp16 tensor cores, fp32 accumulate)
    {
        int blocks = (N_NODES + MTILE - 1) / MTILE;   // 1563
        gemm_kernel<<<blocks, 128>>>(h);
    }

    // 3) SpMM + bias + relu  (2 nodes per warp)
    {
        int nodes_per_block = 16;            // 8 warps x 2
        int blocks = (N_NODES + nodes_per_block - 1) / nodes_per_block;  // 6250
        spmm_kernel<<<blocks, 256>>>(edge_cols, edge_vals, b, out);
    }
}

// round 13
// speedup vs baseline: 1.1506x; 1.1506x over previous
#include <cuda_runtime.h>
#include <cuda_bf16.h>
#include <cuda_fp16.h>
#include <cstdint>

#define N_NODES 100000
#define D 128

// ---------------- scratch (device globals: no allocations allowed) ----------
__device__ int    g_rowptr[N_NODES + 1];
__device__ __half g_hW[(size_t)N_NODES * D];   // h @ W.T in fp16, 25.6 MB
// Pre-swizzled W fragments for mma.sync m16n8k16 fp16.
__device__ uint2 g_Whf[8 * 16 * 32];

// ---------------- Kernel 1: row_ptr via scatter over sorted rows ------------
__global__ void rowptr_kernel(const int* __restrict__ rows, int n_edges) {
    int e = blockIdx.x * blockDim.x + threadIdx.x;
    if (e >= n_edges) return;
    int b = __ldg(&rows[e]);
    if (e == 0) {
        for (int i = 0; i <= b; i++) g_rowptr[i] = 0;
    } else {
        int a = __ldg(&rows[e - 1]);
        for (int i = a + 1; i <= b; i++) g_rowptr[i] = e;
    }
    if (e == n_edges - 1) {
        for (int i = b + 1; i <= N_NODES; i++) g_rowptr[i] = n_edges;
    }
}

// ---------------- Kernel 1b: W fragment prep (fp16) -------------------------
__device__ __forceinline__ uint32_t pack2_h16(float x, float y) {
    __half2 v = __floats2half2_rn(x, y);
    return *(uint32_t*)&v;
}

__global__ void wprep_kernel(const float* __restrict__ W) {
    int t = blockIdx.x * blockDim.x + threadIdx.x;   // 0..4095
    if (t >= 8 * 16 * 32) return;
    int lane  = t & 31;
    int ntile = (t >> 5) & 15;
    int kstep = t >> 9;

    int n  = ntile * 8 + (lane >> 2);
    int k0 = kstep * 16 + (lane & 3) * 2;

    float w00 = __ldg(&W[n * 128 + k0]);
    float w01 = __ldg(&W[n * 128 + k0 + 1]);
    float w10 = __ldg(&W[n * 128 + k0 + 8]);
    float w11 = __ldg(&W[n * 128 + k0 + 9]);

    uint2 f;
    f.x = pack2_h16(w00, w01);
    f.y = pack2_h16(w10, w11);
    g_Whf[t] = f;
}

// ---------------- Kernel 2: g = h @ W.T, smem-staged fp16 mma ----------------
// (unchanged from R10/R11 — measured improvement)
#define MTILE 64
#define APAD  136

__device__ __forceinline__ void mma_f16(float* c, const uint32_t* a, uint2 b) {
    asm volatile(
        "mma.sync.aligned.m16n8k16.row.col.f32.f16.f16.f32 "
        "{%0,%1,%2,%3}, {%4,%5,%6,%7}, {%8,%9}, {%0,%1,%2,%3};"
        : "+f"(c[0]), "+f"(c[1]), "+f"(c[2]), "+f"(c[3])
        : "r"(a[0]), "r"(a[1]), "r"(a[2]), "r"(a[3]), "r"(b.x), "r"(b.y));
}

__global__ void __launch_bounds__(128, 4) gemm_kernel(
    const float* __restrict__ A)   // h [N_NODES, 128]
{
    __shared__ __half sA[MTILE * APAD];   // 17.4 KB

    const int tid    = threadIdx.x;
    const int lane   = tid & 31;
    const int warp   = tid >> 5;
    const int m_base = blockIdx.x * MTILE;

    #pragma unroll
    for (int q = 0; q < 16; q++) {
        int idx = q * 128 + tid;          // 0..2047
        int row = idx >> 5;
        int c4  = idx & 31;
        int rsrc = min(m_base + row, N_NODES - 1);
        float4 v = __ldg(&((const float4*)A)[(size_t)rsrc * 32 + c4]);
        __half2 p0 = __floats2half2_rn(v.x, v.y);
        __half2 p1 = __floats2half2_rn(v.z, v.w);
        *(__half2*)&sA[row * APAD + c4 * 4]     = p0;
        *(__half2*)&sA[row * APAD + c4 * 4 + 2] = p1;
    }
    __syncthreads();

    const int grp  = lane >> 2;
    const int quad = lane & 3;
    const int mrow = (warp >> 1) * 32;
    const int ntb  = (warp & 1) * 8;

    float acc[2][8][4];
    #pragma unroll
    for (int f = 0; f < 2; f++)
        #pragma unroll
        for (int nt = 0; nt < 8; nt++)
            #pragma unroll
            for (int i = 0; i < 4; i++) acc[f][nt][i] = 0.f;

    #pragma unroll
    for (int kstep = 0; kstep < 8; kstep++) {
        int kb = kstep * 16 + quad * 2;
        uint32_t a[2][4];
        #pragma unroll
        for (int f = 0; f < 2; f++) {
            int r = mrow + f * 16 + grp;
            a[f][0] = *(uint32_t*)&sA[r * APAD + kb];
            a[f][1] = *(uint32_t*)&sA[(r + 8) * APAD + kb];
            a[f][2] = *(uint32_t*)&sA[r * APAD + kb + 8];
            a[f][3] = *(uint32_t*)&sA[(r + 8) * APAD + kb + 8];
        }
        #pragma unroll
        for (int nt = 0; nt < 8; nt++) {
            uint2 wh = __ldg(&g_Whf[(kstep * 16 + ntb + nt) * 32 + lane]);
            mma_f16(acc[0][nt], a[0], wh);
            mma_f16(acc[1][nt], a[1], wh);
        }
    }
    __syncthreads();

    #pragma unroll
    for (int f = 0; f < 2; f++) {
        #pragma unroll
        for (int nt = 0; nt < 8; nt++) {
            int col = (ntb + nt) * 8 + quad * 2;
            int r0  = mrow + f * 16 + grp;
            *(__half2*)&sA[r0 * APAD + col] =
                __floats2half2_rn(acc[f][nt][0], acc[f][nt][1]);
            *(__half2*)&sA[(r0 + 8) * APAD + col] =
                __floats2half2_rn(acc[f][nt][2], acc[f][nt][3]);
        }
    }
    __syncthreads();

    #pragma unroll
    for (int q = 0; q < 8; q++) {
        int idx = q * 128 + tid;          // 0..1023
        int row = idx >> 4;
        int c16 = idx & 15;
        int rdst = m_base + row;
        if (rdst < N_NODES) {
            uint4 v = *(uint4*)&sA[row * APAD + c16 * 8];
            *(uint4*)&g_hW[(size_t)rdst * 128 + c16 * 8] = v;
        }
    }
}

// ---------------- Kernel 3: SpMM, half-warp per node, fp32 accum ------------
// R11 structure (static unroll-16 inner body, fp32 scalar FMA — identical
// summation order) + double-buffered edge-chunk loads: (c,v) for trip t+1
// are issued before trip t's 16 gathers, hiding the edge-list load latency.
__global__ void __launch_bounds__(256) spmm_kernel(
    const int*   __restrict__ cols,
    const float* __restrict__ vals,
    const float* __restrict__ bias,
    float*       __restrict__ out)
{
    const int warp_id = (blockIdx.x * blockDim.x + threadIdx.x) >> 5;
    const unsigned lane = threadIdx.x & 31;
    const unsigned hl   = lane & 15;          // lane within half-warp
    const int nid = warp_id * 2 + (int)(lane >> 4);
    if (warp_id * 2 >= N_NODES) return;

    int start = 0, end = 0;
    if (nid < N_NODES) {
        start = g_rowptr[nid];
        end   = g_rowptr[nid + 1];
    }
    const int deg  = end - start;
    const int odeg = __shfl_xor_sync(0xffffffffu, deg, 16);
    const int ntrips = (max(deg, odeg) + 15) >> 4;   // warp-uniform

    const uint4* __restrict__ g4 = ((const uint4*)g_hW) + hl;   // row = 16 uint4

    float acc[8];
    #pragma unroll
    for (int i = 0; i < 8; i++) acc[i] = 0.f;

    // Prime trip 0's edge chunk.
    int   c = 0; float v = 0.f;
    {
        int e = start + (int)hl;
        if (ntrips > 0 && e < end) {
            c = __ldg(&cols[e]);
            v = __ldg(&vals[e]);
        }
    }

    for (int t = 0; t < ntrips; t++) {
        // Prefetch trip t+1's chunk before consuming trip t.
        int   cn = 0; float vn = 0.f;
        {
            int e = start + (t + 1) * 16 + (int)hl;
            if (t + 1 < ntrips && e < end) {
                cn = __ldg(&cols[e]);
                vn = __ldg(&vals[e]);
            }
        }
        #pragma unroll
        for (int j = 0; j < 16; j++) {
            unsigned cj = (unsigned)__shfl_sync(0xffffffffu, c, j, 16);
            float    vj = __shfl_sync(0xffffffffu, v, j, 16);
            uint4 raw = __ldg(&g4[cj * 16u]);
            float2 f0 = __half22float2(*(__half2*)&raw.x);
            float2 f1 = __half22float2(*(__half2*)&raw.y);
            float2 f2 = __half22float2(*(__half2*)&raw.z);
            float2 f3 = __half22float2(*(__half2*)&raw.w);
            acc[0] = fmaf(vj, f0.x, acc[0]);
            acc[1] = fmaf(vj, f0.y, acc[1]);
            acc[2] = fmaf(vj, f1.x, acc[2]);
            acc[3] = fmaf(vj, f1.y, acc[3]);
            acc[4] = fmaf(vj, f2.x, acc[4]);
            acc[5] = fmaf(vj, f2.y, acc[5]);
            acc[6] = fmaf(vj, f3.x, acc[6]);
            acc[7] = fmaf(vj, f3.y, acc[7]);
        }
        c = cn; v = vn;
    }

    if (nid < N_NODES) {
        const float4* b4 = ((const float4*)bias) + hl * 2;
        float4 ba = __ldg(&b4[0]);
        float4 bb = __ldg(&b4[1]);
        float4 o0, o1;
        o0.x = fmaxf(acc[0] + ba.x, 0.f);
        o0.y = fmaxf(acc[1] + ba.y, 0.f);
        o0.z = fmaxf(acc[2] + ba.z, 0.f);
        o0.w = fmaxf(acc[3] + ba.w, 0.f);
        o1.x = fmaxf(acc[4] + bb.x, 0.f);
        o1.y = fmaxf(acc[5] + bb.y, 0.f);
        o1.z = fmaxf(acc[6] + bb.z, 0.f);
        o1.w = fmaxf(acc[7] + bb.w, 0.f);
        float4* orow = ((float4*)out) + (size_t)nid * 32 + hl * 2;
        orow[0] = o0;
        orow[1] = o1;
    }
}

// ---------------- launch ----------------------------------------------------
extern "C" void kernel_launch(void* const* d_in, const int* in_sizes, int n_in,
                              void* d_out, int out_size)
{
    const int*   edge_rows = (const int*)  d_in[0];
    const int*   edge_cols = (const int*)  d_in[1];
    const float* edge_vals = (const float*)d_in[2];
    const float* h         = (const float*)d_in[3];
    const float* W         = (const float*)d_in[4];
    const float* b         = (const float*)d_in[5];
    float*       out       = (float*)d_out;

    const int n_edges = in_sizes[0];

    // 1) row_ptr (scatter) + W fragment prep
    {
        int threads = 256;
        int blocks  = (n_edges + threads - 1) / threads;
        rowptr_kernel<<<blocks, threads>>>(edge_rows, n_edges);
        wprep_kernel<<<16, 256>>>(W);
    }

    // 2) g = h @ W.T  (smem-staged fp16 tensor cores, fp32 accumulate)
    {
        int blocks = (N_NODES + MTILE - 1) / MTILE;   // 1563
        gemm_kernel<<<blocks, 128>>>(h);
    }

    // 3) SpMM + bias + relu  (2 nodes per warp)
    {
        int nodes_per_block = 16;            // 8 warps x 2
        int blocks = (N_NODES + nodes_per_block - 1) / nodes_per_block;  // 6250
        spmm_kernel<<<blocks, 256>>>(edge_cols, edge_vals, b, out);
    }
}